// round 1
// baseline (speedup 1.0000x reference)
#include <cuda_runtime.h>
#include <math.h>

#define TOKENS  2048
#define HIDDEN  2048
#define INTER   1408
#define EXPERTS 16
#define TOPK    2
#define MAXPAIRS (TOKENS*TOPK)

// ---------------- scratch (static device globals; no allocation) ----------------
__device__ int   g_cnt[EXPERTS];
__device__ int   g_off[EXPERTS + 1];
__device__ int   g_tok[EXPERTS * TOKENS];     // token id per (expert, local slot)
__device__ int   g_te[MAXPAIRS];              // expert id per (token, k)
__device__ int   g_tslot[MAXPAIRS];           // local slot per (token, k)
__device__ float g_tw[MAXPAIRS];              // routing weight per (token, k)
__device__ float g_logits[TOKENS * EXPERTS];
__device__ float g_gate[(size_t)MAXPAIRS * INTER];   // gate proj, then h (in place)
__device__ float g_up[(size_t)MAXPAIRS * INTER];
__device__ float g_y[(size_t)MAXPAIRS * HIDDEN];     // per-pair down-proj output

// ---------------- tiny helpers ----------------
__device__ __forceinline__ float sigmoidf_fast(float x) {
    return 1.0f / (1.0f + __expf(-x));
}

// ---------------- kernel 1: zero counters ----------------
__global__ void zero_cnt_kernel() {
    if (threadIdx.x < EXPERTS) g_cnt[threadIdx.x] = 0;
}

// ---------------- kernel 2: router logits  logits[t][e] = X[t] . Wg[:,e] ----------
__global__ void router_logits_kernel(const float* __restrict__ X,
                                     const float* __restrict__ Wg) {
    int idx = blockIdx.x * blockDim.x + threadIdx.x;   // TOKENS*EXPERTS threads
    int t = idx >> 4;
    int e = idx & 15;
    const float* xr = X + (size_t)t * HIDDEN;
    float s0 = 0.f, s1 = 0.f, s2 = 0.f, s3 = 0.f;
    #pragma unroll 4
    for (int k = 0; k < HIDDEN; k += 4) {
        s0 = fmaf(xr[k + 0], Wg[(k + 0) * EXPERTS + e], s0);
        s1 = fmaf(xr[k + 1], Wg[(k + 1) * EXPERTS + e], s1);
        s2 = fmaf(xr[k + 2], Wg[(k + 2) * EXPERTS + e], s2);
        s3 = fmaf(xr[k + 3], Wg[(k + 3) * EXPERTS + e], s3);
    }
    g_logits[idx] = (s0 + s1) + (s2 + s3);
}

// ---------------- kernel 3: top-2 (sigmoid monotonic -> top-k on logits) ----------
__global__ void router_topk_kernel() {
    int t = blockIdx.x * blockDim.x + threadIdx.x;
    if (t >= TOKENS) return;
    float l[EXPERTS];
    #pragma unroll
    for (int e = 0; e < EXPERTS; e++) l[e] = g_logits[t * EXPERTS + e];

    // jax.lax.top_k tie rule: earliest index wins -> strict '>' scans
    int e1 = 0; float v1 = l[0];
    #pragma unroll
    for (int e = 1; e < EXPERTS; e++) if (l[e] > v1) { v1 = l[e]; e1 = e; }
    int e2 = -1; float v2 = -3.4e38f;
    #pragma unroll
    for (int e = 0; e < EXPERTS; e++) {
        if (e == e1) continue;
        if (l[e] > v2) { v2 = l[e]; e2 = e; }
    }
    float w1 = sigmoidf_fast(v1);
    float w2 = sigmoidf_fast(v2);
    float inv = 1.0f / (w1 + w2);
    w1 *= inv; w2 *= inv;

    int s1 = atomicAdd(&g_cnt[e1], 1);
    int s2 = atomicAdd(&g_cnt[e2], 1);
    g_tok[e1 * TOKENS + s1] = t;
    g_tok[e2 * TOKENS + s2] = t;
    g_te[2 * t + 0] = e1;  g_tslot[2 * t + 0] = s1;  g_tw[2 * t + 0] = w1;
    g_te[2 * t + 1] = e2;  g_tslot[2 * t + 1] = s2;  g_tw[2 * t + 1] = w2;
}

// ---------------- kernel 4: exclusive prefix of counts ----------------
__global__ void offsets_kernel() {
    if (threadIdx.x == 0 && blockIdx.x == 0) {
        int a = 0;
        for (int e = 0; e < EXPERTS; e++) { g_off[e] = a; a += g_cnt[e]; }
        g_off[EXPERTS] = a;   // == MAXPAIRS
    }
}

// ---------------- grouped GEMM: 128x128 tile, BK=16, 256 thr, 8x8/thread --------
// MODE 0: Out=g_gate, A = gathered X rows (K=HIDDEN, N=INTER)
// MODE 1: Out=g_up,   A = gathered X rows (K=HIDDEN, N=INTER)
// MODE 2: Out=g_y,    A = g_gate rows (h)  (K=INTER,  N=HIDDEN)
template <int MODE>
__global__ __launch_bounds__(256, 2)
void gemm_expert_kernel(const float* __restrict__ X,
                        const float* __restrict__ Wbase) {
    constexpr int Kdim = (MODE == 2) ? INTER : HIDDEN;
    constexpr int Ndim = (MODE == 2) ? HIDDEN : INTER;

    const int e  = blockIdx.z;
    const int ne = g_cnt[e];
    const int m0 = blockIdx.x * 128;
    if (m0 >= ne) return;
    const int n0  = blockIdx.y * 128;
    const int off = g_off[e];
    const float* __restrict__ W = Wbase + (size_t)e * Kdim * Ndim;
    float* __restrict__ Out = (MODE == 0) ? g_gate : (MODE == 1) ? g_up : g_y;

    __shared__ float As[128][16];
    __shared__ float Bs[16][128];

    const int tid = threadIdx.x;
    const int tx  = tid & 15;
    const int ty  = tid >> 4;

    // A-load assignments (fixed across K loop)
    const int lr0 = tid >> 2;            // 0..63
    const int lr1 = lr0 + 64;            // 64..127
    const int c4  = (tid & 3) * 4;       // 0,4,8,12
    const float* a0 = nullptr;
    const float* a1 = nullptr;
    {
        int r = m0 + lr0;
        if (r < ne) {
            if (MODE == 2) a0 = g_gate + (size_t)(off + r) * Kdim;
            else           a0 = X + (size_t)g_tok[e * TOKENS + r] * Kdim;
        }
        r = m0 + lr1;
        if (r < ne) {
            if (MODE == 2) a1 = g_gate + (size_t)(off + r) * Kdim;
            else           a1 = X + (size_t)g_tok[e * TOKENS + r] * Kdim;
        }
    }
    // B-load assignments
    const int brow = tid >> 5;           // 0..7 (second load adds +8)
    const int bc4  = (tid & 31) * 4;     // 0..124

    float acc[8][8];
    #pragma unroll
    for (int i = 0; i < 8; i++)
        #pragma unroll
        for (int j = 0; j < 8; j++) acc[i][j] = 0.f;

    for (int k0 = 0; k0 < Kdim; k0 += 16) {
        float4 va0 = a0 ? *(const float4*)(a0 + k0 + c4) : make_float4(0, 0, 0, 0);
        float4 va1 = a1 ? *(const float4*)(a1 + k0 + c4) : make_float4(0, 0, 0, 0);
        float4 vb0 = *(const float4*)(W + (size_t)(k0 + brow)     * Ndim + n0 + bc4);
        float4 vb1 = *(const float4*)(W + (size_t)(k0 + brow + 8) * Ndim + n0 + bc4);

        __syncthreads();   // previous tile fully consumed
        *(float4*)&As[lr0][c4]      = va0;
        *(float4*)&As[lr1][c4]      = va1;
        *(float4*)&Bs[brow][bc4]     = vb0;
        *(float4*)&Bs[brow + 8][bc4] = vb1;
        __syncthreads();

        #pragma unroll
        for (int kk = 0; kk < 16; kk++) {
            float a[8];
            #pragma unroll
            for (int i = 0; i < 8; i++) a[i] = As[ty * 8 + i][kk];
            float4 bb0 = *(const float4*)&Bs[kk][tx * 4];
            float4 bb1 = *(const float4*)&Bs[kk][tx * 4 + 64];
            float b[8] = {bb0.x, bb0.y, bb0.z, bb0.w, bb1.x, bb1.y, bb1.z, bb1.w};
            #pragma unroll
            for (int i = 0; i < 8; i++)
                #pragma unroll
                for (int j = 0; j < 8; j++)
                    acc[i][j] = fmaf(a[i], b[j], acc[i][j]);
        }
    }

    #pragma unroll
    for (int i = 0; i < 8; i++) {
        int r = m0 + ty * 8 + i;
        if (r < ne) {
            float* o = Out + (size_t)(off + r) * Ndim + n0;
            float4 v0 = make_float4(acc[i][0], acc[i][1], acc[i][2], acc[i][3]);
            float4 v1 = make_float4(acc[i][4], acc[i][5], acc[i][6], acc[i][7]);
            *(float4*)(o + tx * 4)      = v0;
            *(float4*)(o + tx * 4 + 64) = v1;
        }
    }
}

// ---------------- kernel: h = silu(gate) * up, in place into g_gate ----------
__global__ void silu_mul_kernel() {
    size_t idx = (size_t)blockIdx.x * blockDim.x + threadIdx.x;  // MAXPAIRS*INTER/4
    float4 g = *(const float4*)(g_gate + 4 * idx);
    float4 u = *(const float4*)(g_up   + 4 * idx);
    float4 r;
    r.x = g.x * sigmoidf_fast(g.x) * u.x;
    r.y = g.y * sigmoidf_fast(g.y) * u.y;
    r.z = g.z * sigmoidf_fast(g.z) * u.z;
    r.w = g.w * sigmoidf_fast(g.w) * u.w;
    *(float4*)(g_gate + 4 * idx) = r;
}

// ---------------- kernel: out[t] = w0*y[p0] + w1*y[p1] (deterministic) ----------
__global__ void combine_kernel(float* __restrict__ out) {
    int idx = blockIdx.x * blockDim.x + threadIdx.x;   // TOKENS*HIDDEN/4
    int t = idx / (HIDDEN / 4);
    int c = idx % (HIDDEN / 4);
    int e0 = g_te[2 * t], e1 = g_te[2 * t + 1];
    size_t p0 = (size_t)g_off[e0] + g_tslot[2 * t];
    size_t p1 = (size_t)g_off[e1] + g_tslot[2 * t + 1];
    float w0 = g_tw[2 * t], w1 = g_tw[2 * t + 1];
    float4 y0 = *(const float4*)(g_y + p0 * HIDDEN + 4 * c);
    float4 y1 = *(const float4*)(g_y + p1 * HIDDEN + 4 * c);
    float4 r;
    r.x = w0 * y0.x + w1 * y1.x;
    r.y = w0 * y0.y + w1 * y1.y;
    r.z = w0 * y0.z + w1 * y1.z;
    r.w = w0 * y0.w + w1 * y1.w;
    *(float4*)(out + (size_t)t * HIDDEN + 4 * c) = r;
}

// ---------------- launcher ----------------
extern "C" void kernel_launch(void* const* d_in, const int* in_sizes, int n_in,
                              void* d_out, int out_size) {
    const float* X   = (const float*)d_in[0];  // [T, H]
    const float* Wg  = (const float*)d_in[1];  // [H, E]
    const float* Wgp = (const float*)d_in[2];  // [E, H, I]
    const float* Wup = (const float*)d_in[3];  // [E, H, I]
    const float* Wdp = (const float*)d_in[4];  // [E, I, H]
    float* out = (float*)d_out;                // [T, H]

    zero_cnt_kernel<<<1, 32>>>();
    router_logits_kernel<<<(TOKENS * EXPERTS) / 256, 256>>>(X, Wg);
    router_topk_kernel<<<(TOKENS + 255) / 256, 256>>>();
    offsets_kernel<<<1, 1>>>();

    dim3 grid_gu(TOKENS / 128, INTER / 128, EXPERTS);    // (16, 11, 16)
    gemm_expert_kernel<0><<<grid_gu, 256>>>(X, Wgp);
    gemm_expert_kernel<1><<<grid_gu, 256>>>(X, Wup);

    silu_mul_kernel<<<(MAXPAIRS * (INTER / 4)) / 256, 256>>>();

    dim3 grid_dn(TOKENS / 128, HIDDEN / 128, EXPERTS);   // (16, 16, 16)
    gemm_expert_kernel<2><<<grid_dn, 256>>>(nullptr, Wdp);

    combine_kernel<<<(TOKENS * (HIDDEN / 4)) / 256, 256>>>(out);
}